// round 4
// baseline (speedup 1.0000x reference)
#include <cuda_runtime.h>

#define NN 50000
#define NE 800000
#define ET (NE + NN)        // 850000 edges incl. self loops
#define D 64
#define H 6
#define HD 384
#define BATCH 1024

typedef unsigned long long u64;

// ---------------- f32x2 packed helpers (sm_100+) -----------------------------
__device__ __forceinline__ u64 pk2(float x, float y) {
    u64 r; asm("mov.b64 %0, {%1, %2};" : "=l"(r) : "f"(x), "f"(y)); return r;
}
__device__ __forceinline__ void fma2(u64& d, u64 a, u64 b) {
    asm("fma.rn.f32x2 %0, %1, %2, %0;" : "+l"(d) : "l"(a), "l"(b));
}
__device__ __forceinline__ float2 upk2(u64 v) {
    float2 r; asm("mov.b64 {%0, %1}, %2;" : "=f"(r.x), "=f"(r.y) : "l"(v)); return r;
}

// ---------------- scratch (device globals; no allocations allowed) ----------
__device__ float g_xp[(size_t)NN * HD];     // transformed feats; reused as x2^T at the end
__device__ float g_as[NN * H];
__device__ float g_ad[NN * H];
__device__ float g_x1[NN * D];
__device__ float g_x2[NN * D];
__device__ int   g_rowptr[NN + 1];
__device__ int   g_cursor[NN];
__device__ int   g_esrc[ET];
__device__ float g_pool[BATCH * D];

// ---------------- CSR build --------------------------------------------------
__global__ void k_init_deg() {
    int i = blockIdx.x * blockDim.x + threadIdx.x;
    if (i < NN) g_cursor[i] = 1;                 // self loop
}

__global__ void k_count(const int* __restrict__ ei) {
    int e = blockIdx.x * blockDim.x + threadIdx.x;
    if (e < NE) atomicAdd(&g_cursor[ei[NE + e]], 1);   // dst = ei[1][e]
}

// single-block scan: thread-serial (49 elems) + shfl block scan. 2 barriers.
__global__ void __launch_bounds__(1024) k_scan() {
    __shared__ int wsum[32];
    int tid = threadIdx.x;
    int lane = tid & 31, warp = tid >> 5;
    int base = tid * 49;
    int s = 0;
    for (int i = 0; i < 49; i++) {
        int idx = base + i;
        if (idx < NN) s += g_cursor[idx];
    }
    // inclusive scan of per-thread sums
    int x = s;
#pragma unroll
    for (int off = 1; off < 32; off <<= 1) {
        int y = __shfl_up_sync(0xffffffffu, x, off);
        if (lane >= off) x += y;
    }
    if (lane == 31) wsum[warp] = x;
    __syncthreads();
    if (warp == 0) {
        int w = wsum[lane];
#pragma unroll
        for (int off = 1; off < 32; off <<= 1) {
            int y = __shfl_up_sync(0xffffffffu, w, off);
            if (lane >= off) w += y;
        }
        wsum[lane] = w;
    }
    __syncthreads();
    int tbase = x - s + (warp ? wsum[warp - 1] : 0);
    int run = tbase;
    for (int i = 0; i < 49; i++) {
        int idx = base + i;
        if (idx < NN) {
            int v = g_cursor[idx];
            g_rowptr[idx] = run;
            g_cursor[idx] = run;
            run += v;
        }
    }
    if (tid == 1023) g_rowptr[NN] = tbase + s;   // == ET
}

__global__ void k_scatter(const int* __restrict__ ei) {
    int i = blockIdx.x * blockDim.x + threadIdx.x;
    if (i < NE) {
        int s = ei[i], d = ei[NE + i];
        int pos = atomicAdd(&g_cursor[d], 1);
        g_esrc[pos] = s;
    } else if (i < ET) {
        int n = i - NE;
        int pos = atomicAdd(&g_cursor[n], 1);
        g_esrc[pos] = n;                          // self loop
    }
}

// ---------------- xp = x @ W  ([NN,64] @ [64,384]) --------------------------
// 192 threads, each handles 2 columns (c, c+192) x 16 rows; f32x2 over k pairs.
__global__ void __launch_bounds__(192) k_gemm_xp(const float* __restrict__ x0,
                                                 const float* __restrict__ W, int layer) {
    __shared__ float xs[16 * 64];
    const float* __restrict__ x = (layer == 0) ? x0 : g_x1;
    int c = threadIdx.x;                // columns c and c+192
    int row0 = blockIdx.x * 16;
    for (int i = c; i < 16 * 64; i += 192)
        xs[i] = x[(size_t)(row0 + (i >> 6)) * 64 + (i & 63)];
    __syncthreads();

    u64 acc0[16], acc1[16];             // packed k-parity partial sums, per column
#pragma unroll
    for (int r = 0; r < 16; r++) { acc0[r] = 0ull; acc1[r] = 0ull; }

#pragma unroll 4
    for (int k4 = 0; k4 < 16; k4++) {
        int k = 4 * k4;
        float wa0 = W[(k + 0) * HD + c],       wa1 = W[(k + 1) * HD + c];
        float wa2 = W[(k + 2) * HD + c],       wa3 = W[(k + 3) * HD + c];
        float wb0 = W[(k + 0) * HD + c + 192], wb1 = W[(k + 1) * HD + c + 192];
        float wb2 = W[(k + 2) * HD + c + 192], wb3 = W[(k + 3) * HD + c + 192];
        u64 bA01 = pk2(wa0, wa1), bA23 = pk2(wa2, wa3);
        u64 bB01 = pk2(wb0, wb1), bB23 = pk2(wb2, wb3);
#pragma unroll
        for (int r = 0; r < 16; r++) {
            u64 a01 = *(const u64*)&xs[r * 64 + k];      // (xs[k], xs[k+1]) broadcast
            u64 a23 = *(const u64*)&xs[r * 64 + k + 2];
            fma2(acc0[r], a01, bA01);
            fma2(acc0[r], a23, bA23);
            fma2(acc1[r], a01, bB01);
            fma2(acc1[r], a23, bB23);
        }
    }
#pragma unroll
    for (int r = 0; r < 16; r++) {
        float2 p0 = upk2(acc0[r]);
        float2 p1 = upk2(acc1[r]);
        size_t rowoff = (size_t)(row0 + r) * HD;
        g_xp[rowoff + c]       = p0.x + p0.y;
        g_xp[rowoff + c + 192] = p1.x + p1.y;
    }
}

// ---------------- per-node attention dot products ----------------------------
__global__ void __launch_bounds__(256) k_attn(const float* __restrict__ asrc,
                                              const float* __restrict__ adst) {
    int warp = (blockIdx.x * blockDim.x + threadIdx.x) >> 5;
    int lane = threadIdx.x & 31;
    if (warp >= NN) return;
    const float* xpr = &g_xp[(size_t)warp * HD];
    float pa[6], pd[6];
#pragma unroll
    for (int t = 0; t < 6; t++) { pa[t] = 0.f; pd[t] = 0.f; }
#pragma unroll
    for (int j = 0; j < 12; j++) {
        int idx = lane + 32 * j;      // h = j>>1
        float xv = xpr[idx];
        pa[j >> 1] += xv * asrc[idx];
        pd[j >> 1] += xv * adst[idx];
    }
#pragma unroll
    for (int t = 0; t < 6; t++) {
#pragma unroll
        for (int off = 16; off; off >>= 1) {
            pa[t] += __shfl_down_sync(0xffffffffu, pa[t], off);
            pd[t] += __shfl_down_sync(0xffffffffu, pd[t], off);
        }
    }
    if (lane == 0) {
#pragma unroll
        for (int t = 0; t < 6; t++) {
            g_as[warp * 6 + t] = pa[t];
            g_ad[warp * 6 + t] = pd[t];
        }
    }
}

// ---------------- fused softmax-sum + weighted gather-accumulate -------------
// No max pass (logits tiny -> exp safe, math identical). Warp per node.
__global__ void __launch_bounds__(256) k_edge(const float* __restrict__ bias, int layer) {
    int warp = (blockIdx.x * blockDim.x + threadIdx.x) >> 5;
    int lane = threadIdx.x & 31;
    if (warp >= NN) return;
    float* __restrict__ xout = (layer == 0) ? g_x1 : g_x2;
    int n = warp;
    int beg = g_rowptr[n], end = g_rowptr[n + 1];

    float adh[6];
    {
        const float2* adp = (const float2*)(g_ad + n * 6);
        float2 a0 = adp[0], a1 = adp[1], a2 = adp[2];
        adh[0] = a0.x; adh[1] = a0.y; adh[2] = a1.x;
        adh[3] = a1.y; adh[4] = a2.x; adh[5] = a2.y;
    }

    // pass 1: per-head sum of exp(leaky(v)) over incoming edges
    float sm[6];
#pragma unroll
    for (int t = 0; t < 6; t++) sm[t] = 0.f;
    for (int e = beg + lane; e < end; e += 32) {
        int src = g_esrc[e];
        const float2* asp = (const float2*)(g_as + src * 6);
        float2 s0 = asp[0], s1 = asp[1], s2 = asp[2];
        float v[6] = { s0.x + adh[0], s0.y + adh[1], s1.x + adh[2],
                       s1.y + adh[3], s2.x + adh[4], s2.y + adh[5] };
#pragma unroll
        for (int t = 0; t < 6; t++) {
            float u = (v[t] > 0.f) ? v[t] : 0.2f * v[t];
            sm[t] += __expf(u);
        }
    }
#pragma unroll
    for (int t = 0; t < 6; t++)
#pragma unroll
        for (int off = 16; off; off >>= 1)
            sm[t] += __shfl_xor_sync(0xffffffffu, sm[t], off);

    // per-lane scalars for lanes 0..5 (select chains, no dynamic reg index)
    float adh_l = adh[0], inv_l = sm[0];
#pragma unroll
    for (int t = 1; t < 6; t++) {
        if (lane == t) { adh_l = adh[t]; inv_l = sm[t]; }
    }
    inv_l = 1.f / (inv_l + 1e-16f);

    // pass 2: accumulate alpha * xp[src], float4 gathers, 2-edge pipeline
    float4 a0 = make_float4(0.f, 0.f, 0.f, 0.f);
    float4 a1 = a0, a2 = a0;
    int half = lane >> 4;               // h = 2j + half for j-th float4
    int coff = 4 * (lane & 15);

    int e = beg;
    for (; e + 1 < end; e += 2) {
        int s0 = g_esrc[e], s1 = g_esrc[e + 1];
        float al0 = 0.f, al1 = 0.f;
        if (lane < 6) {
            float v0 = g_as[s0 * 6 + lane] + adh_l;
            float v1 = g_as[s1 * 6 + lane] + adh_l;
            v0 = (v0 > 0.f) ? v0 : 0.2f * v0;
            v1 = (v1 > 0.f) ? v1 : 0.2f * v1;
            al0 = __expf(v0) * inv_l;
            al1 = __expf(v1) * inv_l;
        }
        const float* x0r = &g_xp[(size_t)s0 * HD];
        const float* x1r = &g_xp[(size_t)s1 * HD];
        float4 v00 = *(const float4*)(x0r + 0   + 4 * lane);
        float4 v01 = *(const float4*)(x0r + 128 + 4 * lane);
        float4 v02 = *(const float4*)(x0r + 256 + 4 * lane);
        float4 v10 = *(const float4*)(x1r + 0   + 4 * lane);
        float4 v11 = *(const float4*)(x1r + 128 + 4 * lane);
        float4 v12 = *(const float4*)(x1r + 256 + 4 * lane);
#pragma unroll
        for (int j = 0; j < 3; j++) {
            float b0 = __shfl_sync(0xffffffffu, al0, 2 * j + half);
            float b1 = __shfl_sync(0xffffffffu, al1, 2 * j + half);
            float4* acc = (j == 0) ? &a0 : (j == 1) ? &a1 : &a2;
            float4 w0 = (j == 0) ? v00 : (j == 1) ? v01 : v02;
            float4 w1 = (j == 0) ? v10 : (j == 1) ? v11 : v12;
            acc->x += b0 * w0.x + b1 * w1.x;
            acc->y += b0 * w0.y + b1 * w1.y;
            acc->z += b0 * w0.z + b1 * w1.z;
            acc->w += b0 * w0.w + b1 * w1.w;
        }
    }
    if (e < end) {
        int s0 = g_esrc[e];
        float al0 = 0.f;
        if (lane < 6) {
            float v0 = g_as[s0 * 6 + lane] + adh_l;
            v0 = (v0 > 0.f) ? v0 : 0.2f * v0;
            al0 = __expf(v0) * inv_l;
        }
        const float* x0r = &g_xp[(size_t)s0 * HD];
        float4 v00 = *(const float4*)(x0r + 0   + 4 * lane);
        float4 v01 = *(const float4*)(x0r + 128 + 4 * lane);
        float4 v02 = *(const float4*)(x0r + 256 + 4 * lane);
#pragma unroll
        for (int j = 0; j < 3; j++) {
            float b0 = __shfl_sync(0xffffffffu, al0, 2 * j + half);
            float4* acc = (j == 0) ? &a0 : (j == 1) ? &a1 : &a2;
            float4 w0 = (j == 0) ? v00 : (j == 1) ? v01 : v02;
            acc->x += b0 * w0.x;
            acc->y += b0 * w0.y;
            acc->z += b0 * w0.z;
            acc->w += b0 * w0.w;
        }
    }
    // combine 3 heads held by this lane, then the other 3 from lane^16
    float4 s;
    s.x = a0.x + a1.x + a2.x;
    s.y = a0.y + a1.y + a2.y;
    s.z = a0.z + a1.z + a2.z;
    s.w = a0.w + a1.w + a2.w;
    s.x += __shfl_xor_sync(0xffffffffu, s.x, 16);
    s.y += __shfl_xor_sync(0xffffffffu, s.y, 16);
    s.z += __shfl_xor_sync(0xffffffffu, s.z, 16);
    s.w += __shfl_xor_sync(0xffffffffu, s.w, 16);
    if (lane < 16) {
        float4 bv = *(const float4*)(bias + coff);
        float4 o;
        o.x = s.x * (1.f / 6.f) + bv.x;
        o.y = s.y * (1.f / 6.f) + bv.y;
        o.z = s.z * (1.f / 6.f) + bv.z;
        o.w = s.w * (1.f / 6.f) + bv.w;
        *(float4*)(xout + (size_t)n * 64 + coff) = o;
    }
}

// ---------------- transpose x2 [NN,64] -> x2t [64,NN] (into g_xp) ------------
__global__ void k_transpose() {
    __shared__ float tile[32][33];
    int nb = blockIdx.x * 32, db = blockIdx.y * 32;
    int tx = threadIdx.x, ty = threadIdx.y;
#pragma unroll
    for (int i = ty; i < 32; i += 8) {
        int n = nb + i;
        tile[i][tx] = (n < NN) ? g_x2[(size_t)n * D + db + tx] : 0.f;
    }
    __syncthreads();
#pragma unroll
    for (int i = ty; i < 32; i += 8) {
        int n = nb + tx;
        if (n < NN) g_xp[(size_t)(db + i) * NN + n] = tile[tx][i];
    }
}

__global__ void k_zero_pool() {
    int i = blockIdx.x * blockDim.x + threadIdx.x;
    if (i < BATCH * D) g_pool[i] = 0.f;
}

// ---------------- pool = item @ x2   ([1024,50000] @ [50000,64]) -------------
// b-tile 8, 2 K-splits. f32x2: acc packed over n-parity; it-pairs free via LDS.64,
// x2t pairs free from float4 regs (explicit mov.b64 pack).
#define PK 2                      // K-splits
#define KSPAN (NN / PK)           // 25000
__global__ void __launch_bounds__(256) k_pool(const float* __restrict__ item) {
    __shared__ float sit[8][64];
    int t = threadIdx.x;
    int b0 = blockIdx.x * 8;
    int nbase = blockIdx.y * KSPAN;
    int nend  = nbase + KSPAN;
    int g = t >> 4;               // d-group: d = 4g..4g+3 (0..15)
    int q = t & 15;               // n sub-index
    const float* __restrict__ x2t = g_xp;

    u64 accp[8][4];
#pragma unroll
    for (int bb = 0; bb < 8; bb++)
#pragma unroll
        for (int dd = 0; dd < 4; dd++) accp[bb][dd] = 0ull;

    for (int nb0 = nbase; nb0 < nend; nb0 += 64) {
        __syncthreads();
        if (t < 128) {            // fill 8 x 64 item chunk
            int row = t >> 4;
            int n4 = nb0 + 4 * (t & 15);
            float4 v = make_float4(0.f, 0.f, 0.f, 0.f);
            if (n4 < nend) v = *(const float4*)(item + (size_t)(b0 + row) * NN + n4);
            *(float4*)&sit[row][4 * (t & 15)] = v;
        }
        __syncthreads();

        int n0 = nb0 + 4 * q;
        u64 xlo[4], xhi[4];
#pragma unroll
        for (int dd = 0; dd < 4; dd++) {
            float4 xv = *(const float4*)(x2t + (size_t)(4 * g + dd) * NN + n0);
            xlo[dd] = pk2(xv.x, xv.y);
            xhi[dd] = pk2(xv.z, xv.w);
        }
#pragma unroll
        for (int bb = 0; bb < 8; bb++) {
            u64 it01 = *(const u64*)&sit[bb][4 * q];
            u64 it23 = *(const u64*)&sit[bb][4 * q + 2];
#pragma unroll
            for (int dd = 0; dd < 4; dd++) {
                fma2(accp[bb][dd], it01, xlo[dd]);
                fma2(accp[bb][dd], it23, xhi[dd]);
            }
        }
    }
#pragma unroll
    for (int bb = 0; bb < 8; bb++)
#pragma unroll
        for (int dd = 0; dd < 4; dd++) {
            float2 p = upk2(accp[bb][dd]);
            atomicAdd(&g_pool[(b0 + bb) * D + 4 * g + dd], p.x + p.y);
        }
}

// ---------------- MLP head + sigmoid -----------------------------------------
__global__ void __launch_bounds__(128) k_mlp(const int* __restrict__ user,
                                             const float* __restrict__ u_table,
                                             const float* __restrict__ W0,
                                             const float* __restrict__ b0,
                                             const float* __restrict__ W1,
                                             const float* __restrict__ b1,
                                             float* __restrict__ out) {
    __shared__ float vec[128];
    __shared__ float red[128];
    int b = blockIdx.x, t = threadIdx.x;
    if (t < 64) vec[t] = u_table[(size_t)user[b] * 64 + t];
    else        vec[t] = g_pool[b * 64 + (t - 64)];
    __syncthreads();
    float h = b0[t];
#pragma unroll 8
    for (int k = 0; k < 128; k++) h += vec[k] * W0[k * 128 + t];
    red[t] = h * W1[t];
    __syncthreads();
    for (int s = 64; s; s >>= 1) {
        if (t < s) red[t] += red[t + s];
        __syncthreads();
    }
    if (t == 0) {
        float z = red[0] + b1[0];
        out[b] = 1.f / (1.f + expf(-z));
    }
}

// ---------------- launch -----------------------------------------------------
extern "C" void kernel_launch(void* const* d_in, const int* in_sizes, int n_in,
                              void* d_out, int out_size) {
    const int*   user  = (const int*)d_in[0];
    const float* item  = (const float*)d_in[1];
    const int*   eidx  = (const int*)d_in[3];
    const float* u_tab = (const float*)d_in[4];
    const float* i_tab = (const float*)d_in[5];
    const float* W0    = (const float*)d_in[6];
    const float* as0   = (const float*)d_in[7];
    const float* ad0   = (const float*)d_in[8];
    const float* b0    = (const float*)d_in[9];
    const float* W1    = (const float*)d_in[10];
    const float* as1   = (const float*)d_in[11];
    const float* ad1   = (const float*)d_in[12];
    const float* b1    = (const float*)d_in[13];
    const float* lW0   = (const float*)d_in[14];
    const float* lb0   = (const float*)d_in[15];
    const float* lW1   = (const float*)d_in[16];
    const float* lb1   = (const float*)d_in[17];
    float* out = (float*)d_out;

    // CSR by destination
    k_init_deg<<<(NN + 255) / 256, 256>>>();
    k_count<<<(NE + 255) / 256, 256>>>(eidx);
    k_scan<<<1, 1024>>>();
    k_scatter<<<(ET + 255) / 256, 256>>>(eidx);

    // GAT layer 0 (input = i_table)
    k_gemm_xp<<<NN / 16, 192>>>(i_tab, W0, 0);
    k_attn<<<6250, 256>>>(as0, ad0);
    k_edge<<<6250, 256>>>(b0, 0);

    // GAT layer 1 (input = g_x1)
    k_gemm_xp<<<NN / 16, 192>>>(i_tab, W1, 1);
    k_attn<<<6250, 256>>>(as1, ad1);
    k_edge<<<6250, 256>>>(b1, 1);

    // pooling GEMM + MLP head
    k_transpose<<<dim3((NN + 31) / 32, 2), dim3(32, 8)>>>();
    k_zero_pool<<<(BATCH * D + 255) / 256, 256>>>();
    k_pool<<<dim3(BATCH / 8, PK), 256>>>(item);
    k_mlp<<<BATCH, 128>>>(user, u_tab, lW0, lb0, lW1, lb1, out);
}

// round 6
// speedup vs baseline: 1.3976x; 1.3976x over previous
#include <cuda_runtime.h>

#define NN 50000
#define NE 800000
#define ET (NE + NN)        // 850000 edges incl. self loops
#define D 64
#define H 6
#define HD 384
#define BATCH 1024

// ---------------- scratch (device globals; no allocations allowed) ----------
__device__ float g_xp[(size_t)NN * HD];     // transformed feats; reused as x2^T at the end
__device__ float g_as[NN * H];
__device__ float g_ad[NN * H];
__device__ float g_x1[NN * D];
__device__ float g_x2[NN * D];
__device__ int   g_rowptr[NN + 1];
__device__ int   g_cursor[NN];
__device__ int   g_esrc[ET];
__device__ float g_pool[BATCH * D];

// ---------------- CSR build --------------------------------------------------
__global__ void k_init_deg() {
    int i = blockIdx.x * blockDim.x + threadIdx.x;
    if (i < NN) g_cursor[i] = 1;                 // self loop
}

__global__ void k_count(const int* __restrict__ ei) {
    int e = blockIdx.x * blockDim.x + threadIdx.x;
    if (e < NE) atomicAdd(&g_cursor[ei[NE + e]], 1);   // dst = ei[1][e]
}

// single-block scan: thread-serial (49 elems) + shfl block scan. 2 barriers.
__global__ void __launch_bounds__(1024) k_scan() {
    __shared__ int wsum[32];
    int tid = threadIdx.x;
    int lane = tid & 31, warp = tid >> 5;
    int base = tid * 49;
    int s = 0;
    for (int i = 0; i < 49; i++) {
        int idx = base + i;
        if (idx < NN) s += g_cursor[idx];
    }
    int x = s;
#pragma unroll
    for (int off = 1; off < 32; off <<= 1) {
        int y = __shfl_up_sync(0xffffffffu, x, off);
        if (lane >= off) x += y;
    }
    if (lane == 31) wsum[warp] = x;
    __syncthreads();
    if (warp == 0) {
        int w = wsum[lane];
#pragma unroll
        for (int off = 1; off < 32; off <<= 1) {
            int y = __shfl_up_sync(0xffffffffu, w, off);
            if (lane >= off) w += y;
        }
        wsum[lane] = w;
    }
    __syncthreads();
    int tbase = x - s + (warp ? wsum[warp - 1] : 0);
    int run = tbase;
    for (int i = 0; i < 49; i++) {
        int idx = base + i;
        if (idx < NN) {
            int v = g_cursor[idx];
            g_rowptr[idx] = run;
            g_cursor[idx] = run;
            run += v;
        }
    }
    if (tid == 1023) g_rowptr[NN] = tbase + s;   // == ET
}

__global__ void k_scatter(const int* __restrict__ ei) {
    int i = blockIdx.x * blockDim.x + threadIdx.x;
    if (i < NE) {
        int s = ei[i], d = ei[NE + i];
        int pos = atomicAdd(&g_cursor[d], 1);
        g_esrc[pos] = s;
    } else if (i < ET) {
        int n = i - NE;
        int pos = atomicAdd(&g_cursor[n], 1);
        g_esrc[pos] = n;                          // self loop
    }
}

// ---------------- xp = x @ W  ([NN,64] @ [64,384])  (R2 proven version) ------
__global__ void __launch_bounds__(384) k_gemm_xp(const float* __restrict__ x0,
                                                 const float* __restrict__ W, int layer) {
    __shared__ float xs[16 * 64];
    const float* __restrict__ x = (layer == 0) ? x0 : g_x1;
    int c = threadIdx.x;                // output column 0..383
    int row0 = blockIdx.x * 16;
    for (int i = c; i < 16 * 64; i += 384) {
        int r = i >> 6, k = i & 63;
        xs[i] = x[(size_t)(row0 + r) * 64 + k];
    }
    __syncthreads();
    float acc[16];
#pragma unroll
    for (int r = 0; r < 16; r++) acc[r] = 0.f;
#pragma unroll
    for (int k4 = 0; k4 < 16; k4++) {
        float w0 = W[(4 * k4 + 0) * HD + c];
        float w1 = W[(4 * k4 + 1) * HD + c];
        float w2 = W[(4 * k4 + 2) * HD + c];
        float w3 = W[(4 * k4 + 3) * HD + c];
#pragma unroll
        for (int r = 0; r < 16; r++) {
            float4 xv = *(const float4*)&xs[r * 64 + 4 * k4];
            acc[r] += xv.x * w0 + xv.y * w1 + xv.z * w2 + xv.w * w3;
        }
    }
#pragma unroll
    for (int r = 0; r < 16; r++)
        g_xp[(size_t)(row0 + r) * HD + c] = acc[r];
}

// ---------------- per-node attention dot products ----------------------------
__global__ void __launch_bounds__(256) k_attn(const float* __restrict__ asrc,
                                              const float* __restrict__ adst) {
    int warp = (blockIdx.x * blockDim.x + threadIdx.x) >> 5;
    int lane = threadIdx.x & 31;
    if (warp >= NN) return;
    const float* xpr = &g_xp[(size_t)warp * HD];
    float pa[6], pd[6];
#pragma unroll
    for (int t = 0; t < 6; t++) { pa[t] = 0.f; pd[t] = 0.f; }
#pragma unroll
    for (int j = 0; j < 12; j++) {
        int idx = lane + 32 * j;      // h = j>>1
        float xv = xpr[idx];
        pa[j >> 1] += xv * asrc[idx];
        pd[j >> 1] += xv * adst[idx];
    }
#pragma unroll
    for (int t = 0; t < 6; t++) {
#pragma unroll
        for (int off = 16; off; off >>= 1) {
            pa[t] += __shfl_down_sync(0xffffffffu, pa[t], off);
            pd[t] += __shfl_down_sync(0xffffffffu, pd[t], off);
        }
    }
    if (lane == 0) {
#pragma unroll
        for (int t = 0; t < 6; t++) {
            g_as[warp * 6 + t] = pa[t];
            g_ad[warp * 6 + t] = pd[t];
        }
    }
}

// ---------------- fused softmax-sum + weighted gather-accumulate -------------
__global__ void __launch_bounds__(256) k_edge(const float* __restrict__ bias, int layer) {
    int warp = (blockIdx.x * blockDim.x + threadIdx.x) >> 5;
    int lane = threadIdx.x & 31;
    if (warp >= NN) return;
    float* __restrict__ xout = (layer == 0) ? g_x1 : g_x2;
    int n = warp;
    int beg = g_rowptr[n], end = g_rowptr[n + 1];

    float adh[6];
    {
        const float2* adp = (const float2*)(g_ad + n * 6);
        float2 a0 = adp[0], a1 = adp[1], a2 = adp[2];
        adh[0] = a0.x; adh[1] = a0.y; adh[2] = a1.x;
        adh[3] = a1.y; adh[4] = a2.x; adh[5] = a2.y;
    }

    float sm[6];
#pragma unroll
    for (int t = 0; t < 6; t++) sm[t] = 0.f;
    for (int e = beg + lane; e < end; e += 32) {
        int src = g_esrc[e];
        const float2* asp = (const float2*)(g_as + src * 6);
        float2 s0 = asp[0], s1 = asp[1], s2 = asp[2];
        float v[6] = { s0.x + adh[0], s0.y + adh[1], s1.x + adh[2],
                       s1.y + adh[3], s2.x + adh[4], s2.y + adh[5] };
#pragma unroll
        for (int t = 0; t < 6; t++) {
            float u = (v[t] > 0.f) ? v[t] : 0.2f * v[t];
            sm[t] += __expf(u);
        }
    }
#pragma unroll
    for (int t = 0; t < 6; t++)
#pragma unroll
        for (int off = 16; off; off >>= 1)
            sm[t] += __shfl_xor_sync(0xffffffffu, sm[t], off);

    float adh_l = adh[0], inv_l = sm[0];
#pragma unroll
    for (int t = 1; t < 6; t++) {
        if (lane == t) { adh_l = adh[t]; inv_l = sm[t]; }
    }
    inv_l = 1.f / (inv_l + 1e-16f);

    float4 a0 = make_float4(0.f, 0.f, 0.f, 0.f);
    float4 a1 = a0, a2 = a0;
    int half = lane >> 4;
    int coff = 4 * (lane & 15);

    int e = beg;
    for (; e + 1 < end; e += 2) {
        int s0 = g_esrc[e], s1 = g_esrc[e + 1];
        float al0 = 0.f, al1 = 0.f;
        if (lane < 6) {
            float v0 = g_as[s0 * 6 + lane] + adh_l;
            float v1 = g_as[s1 * 6 + lane] + adh_l;
            v0 = (v0 > 0.f) ? v0 : 0.2f * v0;
            v1 = (v1 > 0.f) ? v1 : 0.2f * v1;
            al0 = __expf(v0) * inv_l;
            al1 = __expf(v1) * inv_l;
        }
        const float* x0r = &g_xp[(size_t)s0 * HD];
        const float* x1r = &g_xp[(size_t)s1 * HD];
        float4 v00 = *(const float4*)(x0r + 0   + 4 * lane);
        float4 v01 = *(const float4*)(x0r + 128 + 4 * lane);
        float4 v02 = *(const float4*)(x0r + 256 + 4 * lane);
        float4 v10 = *(const float4*)(x1r + 0   + 4 * lane);
        float4 v11 = *(const float4*)(x1r + 128 + 4 * lane);
        float4 v12 = *(const float4*)(x1r + 256 + 4 * lane);
#pragma unroll
        for (int j = 0; j < 3; j++) {
            float b0 = __shfl_sync(0xffffffffu, al0, 2 * j + half);
            float b1 = __shfl_sync(0xffffffffu, al1, 2 * j + half);
            float4* acc = (j == 0) ? &a0 : (j == 1) ? &a1 : &a2;
            float4 w0 = (j == 0) ? v00 : (j == 1) ? v01 : v02;
            float4 w1 = (j == 0) ? v10 : (j == 1) ? v11 : v12;
            acc->x += b0 * w0.x + b1 * w1.x;
            acc->y += b0 * w0.y + b1 * w1.y;
            acc->z += b0 * w0.z + b1 * w1.z;
            acc->w += b0 * w0.w + b1 * w1.w;
        }
    }
    if (e < end) {
        int s0 = g_esrc[e];
        float al0 = 0.f;
        if (lane < 6) {
            float v0 = g_as[s0 * 6 + lane] + adh_l;
            v0 = (v0 > 0.f) ? v0 : 0.2f * v0;
            al0 = __expf(v0) * inv_l;
        }
        const float* x0r = &g_xp[(size_t)s0 * HD];
        float4 v00 = *(const float4*)(x0r + 0   + 4 * lane);
        float4 v01 = *(const float4*)(x0r + 128 + 4 * lane);
        float4 v02 = *(const float4*)(x0r + 256 + 4 * lane);
#pragma unroll
        for (int j = 0; j < 3; j++) {
            float b0 = __shfl_sync(0xffffffffu, al0, 2 * j + half);
            float4* acc = (j == 0) ? &a0 : (j == 1) ? &a1 : &a2;
            float4 w0 = (j == 0) ? v00 : (j == 1) ? v01 : v02;
            acc->x += b0 * w0.x;
            acc->y += b0 * w0.y;
            acc->z += b0 * w0.z;
            acc->w += b0 * w0.w;
        }
    }
    float4 s;
    s.x = a0.x + a1.x + a2.x;
    s.y = a0.y + a1.y + a2.y;
    s.z = a0.z + a1.z + a2.z;
    s.w = a0.w + a1.w + a2.w;
    s.x += __shfl_xor_sync(0xffffffffu, s.x, 16);
    s.y += __shfl_xor_sync(0xffffffffu, s.y, 16);
    s.z += __shfl_xor_sync(0xffffffffu, s.z, 16);
    s.w += __shfl_xor_sync(0xffffffffu, s.w, 16);
    if (lane < 16) {
        float4 bv = *(const float4*)(bias + coff);
        float4 o;
        o.x = s.x * (1.f / 6.f) + bv.x;
        o.y = s.y * (1.f / 6.f) + bv.y;
        o.z = s.z * (1.f / 6.f) + bv.z;
        o.w = s.w * (1.f / 6.f) + bv.w;
        *(float4*)(xout + (size_t)n * 64 + coff) = o;
    }
}

// ---------------- transpose x2 [NN,64] -> x2t [64,NN] (into g_xp) ------------
__global__ void k_transpose() {
    __shared__ float tile[32][33];
    int nb = blockIdx.x * 32, db = blockIdx.y * 32;
    int tx = threadIdx.x, ty = threadIdx.y;
#pragma unroll
    for (int i = ty; i < 32; i += 8) {
        int n = nb + i;
        tile[i][tx] = (n < NN) ? g_x2[(size_t)n * D + db + tx] : 0.f;
    }
    __syncthreads();
#pragma unroll
    for (int i = ty; i < 32; i += 8) {
        int n = nb + tx;
        if (n < NN) g_xp[(size_t)(db + i) * NN + n] = tile[tx][i];
    }
}

__global__ void k_zero_pool() {
    int i = blockIdx.x * blockDim.x + threadIdx.x;
    if (i < BATCH * D) g_pool[i] = 0.f;
}

// ================= mma.sync tf32 pooling GEMM (3xTF32 compensated) ===========
// pool[1024,64] = item[1024,50000] @ x2t^T,  x2t = g_xp [64][NN]
// Block: 256 thr / 8 warps; warp owns 32 m-rows x 64 n-cols.
// grid (1024/256 = 4, PPK K-splits), atomicAdd K-reduction.

#define PPK 50
#define PKSPAN (NN / PPK)      // 1000, multiple of 8

__device__ __forceinline__ unsigned f2tf(float x) {
    unsigned r; asm("cvt.rna.tf32.f32 %0, %1;" : "=r"(r) : "f"(x)); return r;
}
__device__ __forceinline__ void mma_tf32(float* c, unsigned a0, unsigned a1,
                                         unsigned a2, unsigned a3,
                                         unsigned b0, unsigned b1) {
    asm volatile(
        "mma.sync.aligned.m16n8k8.row.col.f32.tf32.tf32.f32 "
        "{%0,%1,%2,%3}, {%4,%5,%6,%7}, {%8,%9}, {%0,%1,%2,%3};"
        : "+f"(c[0]), "+f"(c[1]), "+f"(c[2]), "+f"(c[3])
        : "r"(a0), "r"(a1), "r"(a2), "r"(a3), "r"(b0), "r"(b1));
}

__global__ void __launch_bounds__(256) k_pool_mma(const float* __restrict__ item) {
    int t = threadIdx.x;
    int wid = t >> 5, lane = t & 31;
    int m0 = blockIdx.x * 256 + wid * 32;       // warp's first m-row
    int kbeg = blockIdx.y * PKSPAN;

    int r = lane >> 2, c = lane & 3;
    const float* pA0 = item + (size_t)(m0 + r) * NN;        // mt0 rows r, r+8
    const float* pA1 = item + (size_t)(m0 + r + 8) * NN;
    const float* pA2 = item + (size_t)(m0 + r + 16) * NN;   // mt1
    const float* pA3 = item + (size_t)(m0 + r + 24) * NN;
    const float* pB  = g_xp + (size_t)(lane >> 2) * NN + c; // n=lane>>2 (per nt +8 rows)

    float acc[2][8][4];
#pragma unroll
    for (int mt = 0; mt < 2; mt++)
#pragma unroll
        for (int nt = 0; nt < 8; nt++)
#pragma unroll
            for (int i = 0; i < 4; i++) acc[mt][nt][i] = 0.f;

    for (int ch = 0; ch < PKSPAN / 8; ch++) {
        int kb = kbeg + ch * 8 + c;
        // A fragments (raw f32), then split hi/lo tf32
        float a00 = pA0[kb], a01 = pA1[kb], a02 = pA0[kb + 4], a03 = pA1[kb + 4];
        float a10 = pA2[kb], a11 = pA3[kb], a12 = pA2[kb + 4], a13 = pA3[kb + 4];
        unsigned ah[2][4], al[2][4];
        ah[0][0] = f2tf(a00); al[0][0] = f2tf(a00 - __uint_as_float(ah[0][0]));
        ah[0][1] = f2tf(a01); al[0][1] = f2tf(a01 - __uint_as_float(ah[0][1]));
        ah[0][2] = f2tf(a02); al[0][2] = f2tf(a02 - __uint_as_float(ah[0][2]));
        ah[0][3] = f2tf(a03); al[0][3] = f2tf(a03 - __uint_as_float(ah[0][3]));
        ah[1][0] = f2tf(a10); al[1][0] = f2tf(a10 - __uint_as_float(ah[1][0]));
        ah[1][1] = f2tf(a11); al[1][1] = f2tf(a11 - __uint_as_float(ah[1][1]));
        ah[1][2] = f2tf(a12); al[1][2] = f2tf(a12 - __uint_as_float(ah[1][2]));
        ah[1][3] = f2tf(a13); al[1][3] = f2tf(a13 - __uint_as_float(ah[1][3]));

        int kbb = kbeg + ch * 8;                // B k-base (k = kbb + c via pB offset)
#pragma unroll
        for (int nt = 0; nt < 8; nt++) {
            const float* bp = pB + (size_t)nt * 8 * NN;
            float b0r = bp[kbb];
            float b1r = bp[kbb + 4];
            unsigned bh0 = f2tf(b0r), bh1 = f2tf(b1r);
            unsigned bl0 = f2tf(b0r - __uint_as_float(bh0));
            unsigned bl1 = f2tf(b1r - __uint_as_float(bh1));
#pragma unroll
            for (int mt = 0; mt < 2; mt++) {
                mma_tf32(acc[mt][nt], ah[mt][0], ah[mt][1], ah[mt][2], ah[mt][3], bh0, bh1);
                mma_tf32(acc[mt][nt], ah[mt][0], ah[mt][1], ah[mt][2], ah[mt][3], bl0, bl1);
                mma_tf32(acc[mt][nt], al[mt][0], al[mt][1], al[mt][2], al[mt][3], bh0, bh1);
            }
        }
    }

    // epilogue: D layout c0:(r, 2c) c1:(r, 2c+1) c2:(r+8, 2c) c3:(r+8, 2c+1)
#pragma unroll
    for (int mt = 0; mt < 2; mt++) {
        int row = m0 + mt * 16 + r;
#pragma unroll
        for (int nt = 0; nt < 8; nt++) {
            int col = nt * 8 + 2 * c;
            atomicAdd(&g_pool[row * D + col],           acc[mt][nt][0]);
            atomicAdd(&g_pool[row * D + col + 1],       acc[mt][nt][1]);
            atomicAdd(&g_pool[(row + 8) * D + col],     acc[mt][nt][2]);
            atomicAdd(&g_pool[(row + 8) * D + col + 1], acc[mt][nt][3]);
        }
    }
}

// ---------------- MLP head + sigmoid -----------------------------------------
__global__ void __launch_bounds__(128) k_mlp(const int* __restrict__ user,
                                             const float* __restrict__ u_table,
                                             const float* __restrict__ W0,
                                             const float* __restrict__ b0,
                                             const float* __restrict__ W1,
                                             const float* __restrict__ b1,
                                             float* __restrict__ out) {
    __shared__ float vec[128];
    __shared__ float red[128];
    int b = blockIdx.x, t = threadIdx.x;
    if (t < 64) vec[t] = u_table[(size_t)user[b] * 64 + t];
    else        vec[t] = g_pool[b * 64 + (t - 64)];
    __syncthreads();
    float h = b0[t];
#pragma unroll 8
    for (int k = 0; k < 128; k++) h += vec[k] * W0[k * 128 + t];
    red[t] = h * W1[t];
    __syncthreads();
    for (int s = 64; s; s >>= 1) {
        if (t < s) red[t] += red[t + s];
        __syncthreads();
    }
    if (t == 0) {
        float z = red[0] + b1[0];
        out[b] = 1.f / (1.f + expf(-z));
    }
}

// ---------------- launch -----------------------------------------------------
extern "C" void kernel_launch(void* const* d_in, const int* in_sizes, int n_in,
                              void* d_out, int out_size) {
    const int*   user  = (const int*)d_in[0];
    const float* item  = (const float*)d_in[1];
    const int*   eidx  = (const int*)d_in[3];
    const float* u_tab = (const float*)d_in[4];
    const float* i_tab = (const float*)d_in[5];
    const float* W0    = (const float*)d_in[6];
    const float* as0   = (const float*)d_in[7];
    const float* ad0   = (const float*)d_in[8];
    const float* b0    = (const float*)d_in[9];
    const float* W1    = (const float*)d_in[10];
    const float* as1   = (const float*)d_in[11];
    const float* ad1   = (const float*)d_in[12];
    const float* b1    = (const float*)d_in[13];
    const float* lW0   = (const float*)d_in[14];
    const float* lb0   = (const float*)d_in[15];
    const float* lW1   = (const float*)d_in[16];
    const float* lb1   = (const float*)d_in[17];
    float* out = (float*)d_out;

    // CSR by destination
    k_init_deg<<<(NN + 255) / 256, 256>>>();
    k_count<<<(NE + 255) / 256, 256>>>(eidx);
    k_scan<<<1, 1024>>>();
    k_scatter<<<(ET + 255) / 256, 256>>>(eidx);

    // GAT layer 0 (input = i_table)
    k_gemm_xp<<<NN / 16, 384>>>(i_tab, W0, 0);
    k_attn<<<6250, 256>>>(as0, ad0);
    k_edge<<<6250, 256>>>(b0, 0);

    // GAT layer 1 (input = g_x1)
    k_gemm_xp<<<NN / 16, 384>>>(i_tab, W1, 1);
    k_attn<<<6250, 256>>>(as1, ad1);
    k_edge<<<6250, 256>>>(b1, 1);

    // pooling GEMM (mma.sync tf32, 3x compensated) + MLP head
    k_transpose<<<dim3((NN + 31) / 32, 2), dim3(32, 8)>>>();
    k_zero_pool<<<(BATCH * D + 255) / 256, 256>>>();
    k_pool_mma<<<dim3(BATCH / 256, PPK), 256>>>(item);
    k_mlp<<<BATCH, 128>>>(user, u_tab, lW0, lb0, lW1, lb1, out);
}

// round 8
// speedup vs baseline: 1.4348x; 1.0267x over previous
#include <cuda_runtime.h>

#define NN 50000
#define NE 800000
#define ET (NE + NN)        // 850000 edges incl. self loops
#define D 64
#define H 6
#define HD 384
#define BATCH 1024

// ---------------- scratch (device globals; no allocations allowed) ----------
__device__ float g_xp[(size_t)NN * HD];     // transformed feats; reused as x2^T at the end
__device__ float g_as[NN * H];
__device__ float g_ad[NN * H];
__device__ float g_x1[NN * D];
__device__ float g_x2[NN * D];
__device__ int   g_rowptr[NN + 1];
__device__ int   g_cursor[NN];
__device__ int   g_esrc[ET];
__device__ float g_pool[BATCH * D];
__device__ float g_wad[64 * 12];            // folded attention weights: [k][h(6 src) | h(6 dst)]

// ---------------- mma.sync tf32 helpers (frag layout verified in R6) ---------
__device__ __forceinline__ unsigned f2tf(float x) {
    unsigned r; asm("cvt.rna.tf32.f32 %0, %1;" : "=r"(r) : "f"(x)); return r;
}
__device__ __forceinline__ void mma_tf32(float* c, unsigned a0, unsigned a1,
                                         unsigned a2, unsigned a3,
                                         unsigned b0, unsigned b1) {
    asm volatile(
        "mma.sync.aligned.m16n8k8.row.col.f32.tf32.tf32.f32 "
        "{%0,%1,%2,%3}, {%4,%5,%6,%7}, {%8,%9}, {%0,%1,%2,%3};"
        : "+f"(c[0]), "+f"(c[1]), "+f"(c[2]), "+f"(c[3])
        : "r"(a0), "r"(a1), "r"(a2), "r"(a3), "r"(b0), "r"(b1));
}

// ---------------- CSR build --------------------------------------------------
__global__ void k_init_deg() {
    int i = blockIdx.x * blockDim.x + threadIdx.x;
    if (i < NN) g_cursor[i] = 1;                 // self loop
}

__global__ void k_count(const int* __restrict__ ei) {
    int e = blockIdx.x * blockDim.x + threadIdx.x;
    if (e < NE) atomicAdd(&g_cursor[ei[NE + e]], 1);   // dst = ei[1][e]
}

// single-block scan: thread-serial (49 elems) + shfl block scan. 2 barriers.
__global__ void __launch_bounds__(1024) k_scan() {
    __shared__ int wsum[32];
    int tid = threadIdx.x;
    int lane = tid & 31, warp = tid >> 5;
    int base = tid * 49;
    int s = 0;
    for (int i = 0; i < 49; i++) {
        int idx = base + i;
        if (idx < NN) s += g_cursor[idx];
    }
    int x = s;
#pragma unroll
    for (int off = 1; off < 32; off <<= 1) {
        int y = __shfl_up_sync(0xffffffffu, x, off);
        if (lane >= off) x += y;
    }
    if (lane == 31) wsum[warp] = x;
    __syncthreads();
    if (warp == 0) {
        int w = wsum[lane];
#pragma unroll
        for (int off = 1; off < 32; off <<= 1) {
            int y = __shfl_up_sync(0xffffffffu, w, off);
            if (lane >= off) w += y;
        }
        wsum[lane] = w;
    }
    __syncthreads();
    int tbase = x - s + (warp ? wsum[warp - 1] : 0);
    int run = tbase;
    for (int i = 0; i < 49; i++) {
        int idx = base + i;
        if (idx < NN) {
            int v = g_cursor[idx];
            g_rowptr[idx] = run;
            g_cursor[idx] = run;
            run += v;
        }
    }
    if (tid == 1023) g_rowptr[NN] = tbase + s;   // == ET
}

__global__ void k_scatter(const int* __restrict__ ei) {
    int i = blockIdx.x * blockDim.x + threadIdx.x;
    if (i < NE) {
        int s = ei[i], d = ei[NE + i];
        int pos = atomicAdd(&g_cursor[d], 1);
        g_esrc[pos] = s;
    } else if (i < ET) {
        int n = i - NE;
        int pos = atomicAdd(&g_cursor[n], 1);
        g_esrc[pos] = n;                          // self loop
    }
}

// ---------------- xp = x @ W via mma.sync (3xTF32) ---------------------------
// Block 256 thr / 8 warps; M-tile 32 (2 groups of 16), N = 384 (96 per warp).
// warp: mg = wid>>2, noff = (wid&3)*96 -> 12 n-tiles of 8. K = 64 = 8 k-steps.
__global__ void __launch_bounds__(256) k_gemm_mma(const float* __restrict__ x0,
                                                  const float* __restrict__ W, int layer) {
    const float* __restrict__ x = (layer == 0) ? x0 : g_x1;
    int t = threadIdx.x;
    int wid = t >> 5, lane = t & 31;
    int r = lane >> 2, c = lane & 3;
    int mg = wid >> 2;
    int noff = (wid & 3) * 96;
    int m0 = blockIdx.x * 32 + mg * 16;
    int rowA = m0 + r;                     // A rows rowA, rowA+8
    bool vA = rowA < NN, vB = (rowA + 8) < NN;

    float acc[12][4];
#pragma unroll
    for (int nt = 0; nt < 12; nt++)
#pragma unroll
        for (int i = 0; i < 4; i++) acc[nt][i] = 0.f;

    const float* pA0 = x + (size_t)rowA * 64;
    const float* pA1 = x + (size_t)(rowA + 8) * 64;
    int nlane = noff + r;                  // B n-index base for this thread

#pragma unroll
    for (int k8 = 0; k8 < 8; k8++) {
        int kc = k8 * 8 + c;
        float a00 = vA ? pA0[kc]     : 0.f;
        float a01 = vB ? pA1[kc]     : 0.f;
        float a02 = vA ? pA0[kc + 4] : 0.f;
        float a03 = vB ? pA1[kc + 4] : 0.f;
        unsigned ah0 = f2tf(a00), ah1 = f2tf(a01), ah2 = f2tf(a02), ah3 = f2tf(a03);
        unsigned al0 = f2tf(a00 - __uint_as_float(ah0));
        unsigned al1 = f2tf(a01 - __uint_as_float(ah1));
        unsigned al2 = f2tf(a02 - __uint_as_float(ah2));
        unsigned al3 = f2tf(a03 - __uint_as_float(ah3));

        const float* w0p = W + (size_t)kc * HD + nlane;
        const float* w1p = W + (size_t)(kc + 4) * HD + nlane;
#pragma unroll
        for (int nt = 0; nt < 12; nt++) {
            float b0r = w0p[nt * 8];
            float b1r = w1p[nt * 8];
            unsigned bh0 = f2tf(b0r), bh1 = f2tf(b1r);
            unsigned bl0 = f2tf(b0r - __uint_as_float(bh0));
            unsigned bl1 = f2tf(b1r - __uint_as_float(bh1));
            mma_tf32(acc[nt], ah0, ah1, ah2, ah3, bh0, bh1);
            mma_tf32(acc[nt], ah0, ah1, ah2, ah3, bl0, bl1);
            mma_tf32(acc[nt], al0, al1, al2, al3, bh0, bh1);
        }
    }
    // epilogue: c0->(r,2c) c1->(r,2c+1) c2->(r+8,2c) c3->(r+8,2c+1)
#pragma unroll
    for (int nt = 0; nt < 12; nt++) {
        int n0 = noff + nt * 8 + 2 * c;
        if (vA) *(float2*)&g_xp[(size_t)rowA * HD + n0] = make_float2(acc[nt][0], acc[nt][1]);
        if (vB) *(float2*)&g_xp[(size_t)(rowA + 8) * HD + n0] = make_float2(acc[nt][2], acc[nt][3]);
    }
}

// ---------------- folded attention weights: wad[k][0:6]=W@asrc, [6:12]=W@adst -
__global__ void __launch_bounds__(384) k_prew(const float* __restrict__ W,
                                              const float* __restrict__ asrc,
                                              const float* __restrict__ adst) {
    int t = threadIdx.x;
    int k = t % 64, h = t / 64;           // h in 0..5
    float sa = 0.f, sd = 0.f;
    const float* wr = W + (size_t)k * HD + h * 64;
#pragma unroll 8
    for (int d = 0; d < 64; d++) {
        float wv = wr[d];
        sa += wv * asrc[h * 64 + d];
        sd += wv * adst[h * 64 + d];
    }
    g_wad[k * 12 + h]     = sa;
    g_wad[k * 12 + 6 + h] = sd;
}

// ---------------- as/ad = x @ wad  ([NN,64] @ [64,12]) -----------------------
__global__ void __launch_bounds__(128) k_attn2(const float* __restrict__ x0, int layer) {
    __shared__ float sw[64 * 12];
    const float* __restrict__ x = (layer == 0) ? x0 : g_x1;
    int t = threadIdx.x;
#pragma unroll
    for (int i = t; i < 768; i += 128) sw[i] = g_wad[i];
    __syncthreads();
    int n = blockIdx.x * 128 + t;
    if (n >= NN) return;
    float as[6], ad[6];
#pragma unroll
    for (int h = 0; h < 6; h++) { as[h] = 0.f; ad[h] = 0.f; }
    const float4* xr = (const float4*)(x + (size_t)n * 64);
#pragma unroll
    for (int k4 = 0; k4 < 16; k4++) {
        float4 xv = xr[k4];
        const float* w0 = &sw[(4 * k4) * 12];
#pragma unroll
        for (int h = 0; h < 6; h++) {
            as[h] += xv.x * w0[h]      + xv.y * w0[12 + h]
                   + xv.z * w0[24 + h] + xv.w * w0[36 + h];
            ad[h] += xv.x * w0[6 + h]      + xv.y * w0[18 + h]
                   + xv.z * w0[30 + h] + xv.w * w0[42 + h];
        }
    }
#pragma unroll
    for (int h = 0; h < 6; h++) {
        g_as[n * 6 + h] = as[h];
        g_ad[n * 6 + h] = ad[h];
    }
}

// ---------------- fused softmax-sum + weighted gather-accumulate -------------
__global__ void __launch_bounds__(256) k_edge(const float* __restrict__ bias, int layer) {
    int warp = (blockIdx.x * blockDim.x + threadIdx.x) >> 5;
    int lane = threadIdx.x & 31;
    if (warp >= NN) return;
    float* __restrict__ xout = (layer == 0) ? g_x1 : g_x2;
    int n = warp;
    int beg = g_rowptr[n], end = g_rowptr[n + 1];

    float adh[6];
    {
        const float2* adp = (const float2*)(g_ad + n * 6);
        float2 a0 = adp[0], a1 = adp[1], a2 = adp[2];
        adh[0] = a0.x; adh[1] = a0.y; adh[2] = a1.x;
        adh[3] = a1.y; adh[4] = a2.x; adh[5] = a2.y;
    }

    float sm[6];
#pragma unroll
    for (int t = 0; t < 6; t++) sm[t] = 0.f;
    for (int e = beg + lane; e < end; e += 32) {
        int src = g_esrc[e];
        const float2* asp = (const float2*)(g_as + src * 6);
        float2 s0 = asp[0], s1 = asp[1], s2 = asp[2];
        float v[6] = { s0.x + adh[0], s0.y + adh[1], s1.x + adh[2],
                       s1.y + adh[3], s2.x + adh[4], s2.y + adh[5] };
#pragma unroll
        for (int t = 0; t < 6; t++) {
            float u = (v[t] > 0.f) ? v[t] : 0.2f * v[t];
            sm[t] += __expf(u);
        }
    }
#pragma unroll
    for (int t = 0; t < 6; t++)
#pragma unroll
        for (int off = 16; off; off >>= 1)
            sm[t] += __shfl_xor_sync(0xffffffffu, sm[t], off);

    float adh_l = adh[0], inv_l = sm[0];
#pragma unroll
    for (int t = 1; t < 6; t++) {
        if (lane == t) { adh_l = adh[t]; inv_l = sm[t]; }
    }
    inv_l = 1.f / (inv_l + 1e-16f);

    float4 a0 = make_float4(0.f, 0.f, 0.f, 0.f);
    float4 a1 = a0, a2 = a0;
    int half = lane >> 4;
    int coff = 4 * (lane & 15);

    int e = beg;
    for (; e + 1 < end; e += 2) {
        int s0 = g_esrc[e], s1 = g_esrc[e + 1];
        float al0 = 0.f, al1 = 0.f;
        if (lane < 6) {
            float v0 = g_as[s0 * 6 + lane] + adh_l;
            float v1 = g_as[s1 * 6 + lane] + adh_l;
            v0 = (v0 > 0.f) ? v0 : 0.2f * v0;
            v1 = (v1 > 0.f) ? v1 : 0.2f * v1;
            al0 = __expf(v0) * inv_l;
            al1 = __expf(v1) * inv_l;
        }
        const float* x0r = &g_xp[(size_t)s0 * HD];
        const float* x1r = &g_xp[(size_t)s1 * HD];
        float4 v00 = *(const float4*)(x0r + 0   + 4 * lane);
        float4 v01 = *(const float4*)(x0r + 128 + 4 * lane);
        float4 v02 = *(const float4*)(x0r + 256 + 4 * lane);
        float4 v10 = *(const float4*)(x1r + 0   + 4 * lane);
        float4 v11 = *(const float4*)(x1r + 128 + 4 * lane);
        float4 v12 = *(const float4*)(x1r + 256 + 4 * lane);
#pragma unroll
        for (int j = 0; j < 3; j++) {
            float b0 = __shfl_sync(0xffffffffu, al0, 2 * j + half);
            float b1 = __shfl_sync(0xffffffffu, al1, 2 * j + half);
            float4* acc = (j == 0) ? &a0 : (j == 1) ? &a1 : &a2;
            float4 w0 = (j == 0) ? v00 : (j == 1) ? v01 : v02;
            float4 w1 = (j == 0) ? v10 : (j == 1) ? v11 : v12;
            acc->x += b0 * w0.x + b1 * w1.x;
            acc->y += b0 * w0.y + b1 * w1.y;
            acc->z += b0 * w0.z + b1 * w1.z;
            acc->w += b0 * w0.w + b1 * w1.w;
        }
    }
    if (e < end) {
        int s0 = g_esrc[e];
        float al0 = 0.f;
        if (lane < 6) {
            float v0 = g_as[s0 * 6 + lane] + adh_l;
            v0 = (v0 > 0.f) ? v0 : 0.2f * v0;
            al0 = __expf(v0) * inv_l;
        }
        const float* x0r = &g_xp[(size_t)s0 * HD];
        float4 v00 = *(const float4*)(x0r + 0   + 4 * lane);
        float4 v01 = *(const float4*)(x0r + 128 + 4 * lane);
        float4 v02 = *(const float4*)(x0r + 256 + 4 * lane);
#pragma unroll
        for (int j = 0; j < 3; j++) {
            float b0 = __shfl_sync(0xffffffffu, al0, 2 * j + half);
            float4* acc = (j == 0) ? &a0 : (j == 1) ? &a1 : &a2;
            float4 w0 = (j == 0) ? v00 : (j == 1) ? v01 : v02;
            acc->x += b0 * w0.x;
            acc->y += b0 * w0.y;
            acc->z += b0 * w0.z;
            acc->w += b0 * w0.w;
        }
    }
    float4 s;
    s.x = a0.x + a1.x + a2.x;
    s.y = a0.y + a1.y + a2.y;
    s.z = a0.z + a1.z + a2.z;
    s.w = a0.w + a1.w + a2.w;
    s.x += __shfl_xor_sync(0xffffffffu, s.x, 16);
    s.y += __shfl_xor_sync(0xffffffffu, s.y, 16);
    s.z += __shfl_xor_sync(0xffffffffu, s.z, 16);
    s.w += __shfl_xor_sync(0xffffffffu, s.w, 16);
    if (lane < 16) {
        float4 bv = *(const float4*)(bias + coff);
        float4 o;
        o.x = s.x * (1.f / 6.f) + bv.x;
        o.y = s.y * (1.f / 6.f) + bv.y;
        o.z = s.z * (1.f / 6.f) + bv.z;
        o.w = s.w * (1.f / 6.f) + bv.w;
        *(float4*)(xout + (size_t)n * 64 + coff) = o;
    }
}

// ---------------- transpose x2 [NN,64] -> x2t [64,NN] (into g_xp) ------------
__global__ void k_transpose() {
    __shared__ float tile[32][33];
    int nb = blockIdx.x * 32, db = blockIdx.y * 32;
    int tx = threadIdx.x, ty = threadIdx.y;
#pragma unroll
    for (int i = ty; i < 32; i += 8) {
        int n = nb + i;
        tile[i][tx] = (n < NN) ? g_x2[(size_t)n * D + db + tx] : 0.f;
    }
    __syncthreads();
#pragma unroll
    for (int i = ty; i < 32; i += 8) {
        int n = nb + tx;
        if (n < NN) g_xp[(size_t)(db + i) * NN + n] = tile[tx][i];
    }
}

__global__ void k_zero_pool() {
    int i = blockIdx.x * blockDim.x + threadIdx.x;
    if (i < BATCH * D) g_pool[i] = 0.f;
}

// ================= mma.sync tf32 pooling GEMM (3xTF32 compensated) ===========
#define PPK 50
#define PKSPAN (NN / PPK)      // 1000, multiple of 8

__global__ void __launch_bounds__(256) k_pool_mma(const float* __restrict__ item) {
    int t = threadIdx.x;
    int wid = t >> 5, lane = t & 31;
    int m0 = blockIdx.x * 256 + wid * 32;       // warp's first m-row
    int kbeg = blockIdx.y * PKSPAN;

    int r = lane >> 2, c = lane & 3;
    const float* pA0 = item + (size_t)(m0 + r) * NN;
    const float* pA1 = item + (size_t)(m0 + r + 8) * NN;
    const float* pA2 = item + (size_t)(m0 + r + 16) * NN;
    const float* pA3 = item + (size_t)(m0 + r + 24) * NN;
    const float* pB  = g_xp + (size_t)(lane >> 2) * NN + c;

    float acc[2][8][4];
#pragma unroll
    for (int mt = 0; mt < 2; mt++)
#pragma unroll
        for (int nt = 0; nt < 8; nt++)
#pragma unroll
            for (int i = 0; i < 4; i++) acc[mt][nt][i] = 0.f;

    for (int ch = 0; ch < PKSPAN / 8; ch++) {
        int kb = kbeg + ch * 8 + c;
        float a00 = pA0[kb], a01 = pA1[kb], a02 = pA0[kb + 4], a03 = pA1[kb + 4];
        float a10 = pA2[kb], a11 = pA3[kb], a12 = pA2[kb + 4], a13 = pA3[kb + 4];
        unsigned ah[2][4], al[2][4];
        ah[0][0] = f2tf(a00); al[0][0] = f2tf(a00 - __uint_as_float(ah[0][0]));
        ah[0][1] = f2tf(a01); al[0][1] = f2tf(a01 - __uint_as_float(ah[0][1]));
        ah[0][2] = f2tf(a02); al[0][2] = f2tf(a02 - __uint_as_float(ah[0][2]));
        ah[0][3] = f2tf(a03); al[0][3] = f2tf(a03 - __uint_as_float(ah[0][3]));
        ah[1][0] = f2tf(a10); al[1][0] = f2tf(a10 - __uint_as_float(ah[1][0]));
        ah[1][1] = f2tf(a11); al[1][1] = f2tf(a11 - __uint_as_float(ah[1][1]));
        ah[1][2] = f2tf(a12); al[1][2] = f2tf(a12 - __uint_as_float(ah[1][2]));
        ah[1][3] = f2tf(a13); al[1][3] = f2tf(a13 - __uint_as_float(ah[1][3]));

        int kbb = kbeg + ch * 8;
#pragma unroll
        for (int nt = 0; nt < 8; nt++) {
            const float* bp = pB + (size_t)nt * 8 * NN;
            float b0r = bp[kbb];
            float b1r = bp[kbb + 4];
            unsigned bh0 = f2tf(b0r), bh1 = f2tf(b1r);
            unsigned bl0 = f2tf(b0r - __uint_as_float(bh0));
            unsigned bl1 = f2tf(b1r - __uint_as_float(bh1));
#pragma unroll
            for (int mt = 0; mt < 2; mt++) {
                mma_tf32(acc[mt][nt], ah[mt][0], ah[mt][1], ah[mt][2], ah[mt][3], bh0, bh1);
                mma_tf32(acc[mt][nt], ah[mt][0], ah[mt][1], ah[mt][2], ah[mt][3], bl0, bl1);
                mma_tf32(acc[mt][nt], al[mt][0], al[mt][1], al[mt][2], al[mt][3], bh0, bh1);
            }
        }
    }

#pragma unroll
    for (int mt = 0; mt < 2; mt++) {
        int row = m0 + mt * 16 + r;
#pragma unroll
        for (int nt = 0; nt < 8; nt++) {
            int col = nt * 8 + 2 * c;
            atomicAdd(&g_pool[row * D + col],           acc[mt][nt][0]);
            atomicAdd(&g_pool[row * D + col + 1],       acc[mt][nt][1]);
            atomicAdd(&g_pool[(row + 8) * D + col],     acc[mt][nt][2]);
            atomicAdd(&g_pool[(row + 8) * D + col + 1], acc[mt][nt][3]);
        }
    }
}

// ---------------- MLP head + sigmoid -----------------------------------------
__global__ void __launch_bounds__(128) k_mlp(const int* __restrict__ user,
                                             const float* __restrict__ u_table,
                                             const float* __restrict__ W0,
                                             const float* __restrict__ b0,
                                             const float* __restrict__ W1,
                                             const float* __restrict__ b1,
                                             float* __restrict__ out) {
    __shared__ float vec[128];
    __shared__ float red[128];
    int b = blockIdx.x, t = threadIdx.x;
    if (t < 64) vec[t] = u_table[(size_t)user[b] * 64 + t];
    else        vec[t] = g_pool[b * 64 + (t - 64)];
    __syncthreads();
    float h = b0[t];
#pragma unroll 8
    for (int k = 0; k < 128; k++) h += vec[k] * W0[k * 128 + t];
    red[t] = h * W1[t];
    __syncthreads();
    for (int s = 64; s; s >>= 1) {
        if (t < s) red[t] += red[t + s];
        __syncthreads();
    }
    if (t == 0) {
        float z = red[0] + b1[0];
        out[b] = 1.f / (1.f + expf(-z));
    }
}

// ---------------- launch -----------------------------------------------------
extern "C" void kernel_launch(void* const* d_in, const int* in_sizes, int n_in,
                              void* d_out, int out_size) {
    const int*   user  = (const int*)d_in[0];
    const float* item  = (const float*)d_in[1];
    const int*   eidx  = (const int*)d_in[3];
    const float* u_tab = (const float*)d_in[4];
    const float* i_tab = (const float*)d_in[5];
    const float* W0    = (const float*)d_in[6];
    const float* as0   = (const float*)d_in[7];
    const float* ad0   = (const float*)d_in[8];
    const float* b0    = (const float*)d_in[9];
    const float* W1    = (const float*)d_in[10];
    const float* as1   = (const float*)d_in[11];
    const float* ad1   = (const float*)d_in[12];
    const float* b1    = (const float*)d_in[13];
    const float* lW0   = (const float*)d_in[14];
    const float* lb0   = (const float*)d_in[15];
    const float* lW1   = (const float*)d_in[16];
    const float* lb1   = (const float*)d_in[17];
    float* out = (float*)d_out;

    const int GXP = (NN + 31) / 32;   // 1563 blocks for gemm

    // CSR by destination
    k_init_deg<<<(NN + 255) / 256, 256>>>();
    k_count<<<(NE + 255) / 256, 256>>>(eidx);
    k_scan<<<1, 1024>>>();
    k_scatter<<<(ET + 255) / 256, 256>>>(eidx);

    // GAT layer 0 (input = i_table)
    k_gemm_mma<<<GXP, 256>>>(i_tab, W0, 0);
    k_prew<<<1, 384>>>(W0, as0, ad0);
    k_attn2<<<(NN + 127) / 128, 128>>>(i_tab, 0);
    k_edge<<<6250, 256>>>(b0, 0);

    // GAT layer 1 (input = g_x1)
    k_gemm_mma<<<GXP, 256>>>(i_tab, W1, 1);
    k_prew<<<1, 384>>>(W1, as1, ad1);
    k_attn2<<<(NN + 127) / 128, 128>>>(i_tab, 1);
    k_edge<<<6250, 256>>>(b1, 1);

    // pooling GEMM (mma.sync tf32) + MLP head
    k_transpose<<<dim3((NN + 31) / 32, 2), dim3(32, 8)>>>();
    k_zero_pool<<<(BATCH * D + 255) / 256, 256>>>();
    k_pool_mma<<<dim3(BATCH / 256, PPK), 256>>>(item);
    k_mlp<<<BATCH, 128>>>(user, u_tab, lW0, lb0, lW1, lb1, out);
}